// round 16
// baseline (speedup 1.0000x reference)
#include <cuda_runtime.h>
#include <cuda_bf16.h>
#include <mma.h>
#include <math.h>
#include <stdint.h>

using namespace nvcuda;

#define NTOT 131072
#define DIN 768
#define DH 128
#define DA 32
#define KSEL 64
#define CAND 256
#define CANDCAP 320
#define KC 32
#define NITER 24
#define LCAP 4096
#define NBLK (NTOT / 128)

// ---------------- device scratch (allocation-free) ----------------
__device__ float          g_s[NTOT];                  // approximate attention scores
__device__ float          g_Z;                        // softmax denominator (approx)
__device__ unsigned       g_hist[2048];               // 11-bit score histogram
__device__ float          g_zpart[NBLK];              // per-block sum exp(s)
__device__ int            g_cand[CANDCAP];            // candidate row indices
__device__ int            g_ncand;                    // candidate count
__device__ float          g_sc[CANDCAP];              // exact fp32 scores of candidates
__device__ float          g_xc[CANDCAP * DH];         // exact fp32 x rows of candidates
__device__ float          g_dummy[DH];                // L2-prefetch sink
__device__ __nv_bfloat16  g_Wthi[DH * DIN];           // W1^T bf16  [n][k]

// ---------------- fused kernel smem map (bytes) ----------------
// mainloop: AHI[2] 10240 per buf (128x40 bf16); BHI[2] 10240 per buf
#define OFF_AHI 0
#define OFF_BHI 20480
// epilogue reuse: XS = 8 warps x (32 x 76 f) = 77824 ; W1S 128x32 f = 16384
#define XPITCH 76
#define OFF_XS  0
#define OFF_W1S 77824
#define SM_BYTES 94208

__device__ __forceinline__ uint32_t smem_u32(const void* p) {
    uint32_t a;
    asm("{ .reg .u64 t; cvta.to.shared.u64 t, %1; cvt.u32.u64 %0, t; }" : "=r"(a) : "l"(p));
    return a;
}
__device__ __forceinline__ void cp16(uint32_t s, const void* g) {
    asm volatile("cp.async.cg.shared.global [%0], [%1], 16;" :: "r"(s), "l"(g));
}
__device__ __forceinline__ void cp_commit() { asm volatile("cp.async.commit_group;" ::: "memory"); }
__device__ __forceinline__ void cp_wait0()  { asm volatile("cp.async.wait_group 0;" ::: "memory"); }

__device__ __forceinline__ unsigned f2k(float f) {
    unsigned u = __float_as_uint(f);
    return u ^ ((u & 0x80000000u) ? 0xFFFFFFFFu : 0x80000000u);
}
// single-instruction packed convert: lo = first arg, hi = second
__device__ __forceinline__ uint32_t cvt2(float lo, float hi) {
    uint32_t r;
    asm("cvt.rn.bf16x2.f32 %0, %1, %2;" : "=r"(r) : "f"(hi), "f"(lo));
    return r;
}

// ---------------- kernel 0: W1 -> bf16 transpose, zero hist, L2-warm Wz ----------------
__global__ __launch_bounds__(256) void conv_w1(const float* __restrict__ W1,
                                               const float* __restrict__ Wz) {
    int n = blockIdx.x;
    if (threadIdx.x < 16) g_hist[n * 16 + threadIdx.x] = 0u;
    for (int k = threadIdx.x; k < DIN; k += 256)
        g_Wthi[n * DIN + k] = __float2bfloat16(W1[(size_t)k * DH + n]);
    float acc = 0.f;
    const float* wzb = Wz + (size_t)n * 16 * DH;
    for (int i = threadIdx.x; i < 16 * DH; i += 256) acc += wzb[i];
    __shared__ float red[8];
    #pragma unroll
    for (int off = 16; off; off >>= 1) acc += __shfl_xor_sync(0xffffffffu, acc, off);
    if ((threadIdx.x & 31) == 0) red[threadIdx.x >> 5] = acc;
    __syncthreads();
    if (threadIdx.x == 0) {
        float t = 0.f;
        for (int i = 0; i < 8; i++) t += red[i];
        g_dummy[n] = t;
    }
}

// ---------------- kernel 1: 1-pass bf16 WMMA GEMM, single-sync pipeline ----------------
__global__ __launch_bounds__(256, 2) void fused_main_tc(
    const float* __restrict__ input,
    const float* __restrict__ b1, const float* __restrict__ g1, const float* __restrict__ be1,
    const float* __restrict__ Watt1, const float* __restrict__ batt1,
    const float* __restrict__ g2, const float* __restrict__ be2,
    const float* __restrict__ Watt2, const float* __restrict__ batt2)
{
    extern __shared__ char sm[];
    __shared__ float sarr[128];
    __shared__ float zred[4];
    const uint32_t su = smem_u32(sm);
    __nv_bfloat16* sAhi = (__nv_bfloat16*)(sm + OFF_AHI);

    const int tid = threadIdx.x;
    const int lane = tid & 31, wid = tid >> 5;
    const int wg = wid >> 2;          // 0/1: N half
    const int w4 = wid & 3;           // 0..3: M group of 32 rows
    const int m0 = blockIdx.x * 128;

    // A loader: thread -> (row = tid>>1, 16 floats at half*16)
    const int arow = tid >> 1, ahalf = (tid & 1) << 4;
    const float* abase = input + (size_t)(m0 + arow) * DIN + ahalf;
    // B loader: 2 x 256 slots
    const int brow = tid >> 2, bk8 = (tid & 3) << 3;
    const int brow2 = (tid + 256) >> 2, bk82 = ((tid + 256) & 3) << 3;

    wmma::fragment<wmma::accumulator, 16, 16, 16, float> fc[2][4];
    #pragma unroll
    for (int i = 0; i < 2; i++)
        #pragma unroll
        for (int j = 0; j < 4; j++) wmma::fill_fragment(fc[i][j], 0.0f);

    // prologue: LDG A chunk 0 into regs; issue B chunk 0 cp
    float4 a0, a1, a2, a3;
    a0 = *(const float4*)(abase + 0);
    a1 = *(const float4*)(abase + 4);
    a2 = *(const float4*)(abase + 8);
    a3 = *(const float4*)(abase + 12);
    cp16(su + OFF_BHI + brow * 80 + bk8 * 2,  g_Wthi + brow * DIN + bk8);
    cp16(su + OFF_BHI + brow2 * 80 + bk82 * 2, g_Wthi + brow2 * DIN + bk82);
    cp_commit();

    for (int c = 0; c < NITER; c++) {
        // convert regs (chunk c) -> sAhi[c&1]
        {
            uint32_t off = (uint32_t)(c & 1) * 10240u + (uint32_t)(arow * 80 + ahalf * 2);
            uint4 v0, v1;
            v0.x = cvt2(a0.x, a0.y); v0.y = cvt2(a0.z, a0.w);
            v0.z = cvt2(a1.x, a1.y); v0.w = cvt2(a1.z, a1.w);
            v1.x = cvt2(a2.x, a2.y); v1.y = cvt2(a2.z, a2.w);
            v1.z = cvt2(a3.x, a3.y); v1.w = cvt2(a3.z, a3.w);
            *(uint4*)((char*)sAhi + off)      = v0;
            *(uint4*)((char*)sAhi + off + 16) = v1;
        }
        cp_wait0();                      // B(c) arrived
        __syncthreads();                 // converts visible; MMA(c-1) complete
        if (c + 1 < NITER) {             // issue B(c+1); LDG A(c+1) (overlap MMA below)
            const int k0 = (c + 1) * KC;
            const uint32_t bbuf = ((c + 1) & 1) * 10240u;
            cp16(su + OFF_BHI + bbuf + brow * 80 + bk8 * 2,  g_Wthi + brow * DIN + k0 + bk8);
            cp16(su + OFF_BHI + bbuf + brow2 * 80 + bk82 * 2, g_Wthi + brow2 * DIN + k0 + bk82);
            cp_commit();
            a0 = *(const float4*)(abase + k0 + 0);
            a1 = *(const float4*)(abase + k0 + 4);
            a2 = *(const float4*)(abase + k0 + 8);
            a3 = *(const float4*)(abase + k0 + 12);
        }
        // MMA chunk c
        const __nv_bfloat16* Ac  = (const __nv_bfloat16*)((char*)sAhi + (c & 1) * 10240);
        const __nv_bfloat16* Bhi = (const __nv_bfloat16*)(sm + OFF_BHI + (c & 1) * 10240);
        #pragma unroll
        for (int ks = 0; ks < 2; ks++) {
            wmma::fragment<wmma::matrix_a, 16, 16, 16, __nv_bfloat16, wmma::row_major> fa0, fa1;
            wmma::load_matrix_sync(fa0, Ac + (w4 * 32 + 0)  * 40 + ks * 16, 40);
            wmma::load_matrix_sync(fa1, Ac + (w4 * 32 + 16) * 40 + ks * 16, 40);
            #pragma unroll
            for (int nf = 0; nf < 4; nf++) {
                wmma::fragment<wmma::matrix_b, 16, 16, 16, __nv_bfloat16, wmma::col_major> fb;
                wmma::load_matrix_sync(fb, Bhi + (wg * 64 + nf * 16) * 40 + ks * 16, 40);
                wmma::mma_sync(fc[0][nf], fa0, fb, fc[0][nf]);
                wmma::mma_sync(fc[1][nf], fa1, fb, fc[1][nf]);
            }
        }
    }
    __syncthreads();   // all MMA done before smem reuse

    // -------- epilogue (approx path: s only) --------
    float* xsf = (float*)(sm + OFF_XS);
    float* xs  = xsf + wid * (32 * XPITCH);
    float* W1s = (float*)(sm + OFF_W1S);

    #pragma unroll
    for (int i = 0; i < 2; i++)
        #pragma unroll
        for (int nf = 0; nf < 4; nf++)
            wmma::store_matrix_sync(xs + (i * 16) * XPITCH + nf * 16, fc[i][nf],
                                    XPITCH, wmma::mem_row_major);
    for (int i = tid; i < DH * DA; i += 256) W1s[i] = Watt1[i];
    __syncthreads();

    const float invn = rsqrtf(1.0f + 1e-5f);

    // phase A: BN + ReLU in smem only
    {
        int hr  = lane >> 4;
        int cc4 = (lane & 15) << 2;
        int c0  = wg * 64 + cc4;
        float4 b4 = __ldg((const float4*)(b1  + c0));
        float4 g4 = __ldg((const float4*)(g1  + c0));
        float4 e4 = __ldg((const float4*)(be1 + c0));
        float s0 = g4.x * invn, s1 = g4.y * invn, s2 = g4.z * invn, s3 = g4.w * invn;
        #pragma unroll
        for (int it = 0; it < 16; it++) {
            int r = it * 2 + hr;
            float4 a = *(float4*)(xs + r * XPITCH + cc4);
            float4 v;
            v.x = fmaxf((a.x + b4.x) * s0 + e4.x, 0.f);
            v.y = fmaxf((a.y + b4.y) * s1 + e4.y, 0.f);
            v.z = fmaxf((a.z + b4.z) * s2 + e4.z, 0.f);
            v.w = fmaxf((a.w + b4.w) * s3 + e4.w, 0.f);
            *(float4*)(xs + r * XPITCH + cc4) = v;
        }
    }
    __syncthreads();

    // phase H: warp wid owns rows wid*16..+15; lane = h column
    {
        float* xbase = xsf + (wid >> 1) * (32 * XPITCH) + ((wid & 1) * 16) * XPITCH;
        float acc16[16];
        #pragma unroll
        for (int j = 0; j < 16; j++) acc16[j] = 0.f;
        for (int cc = 0; cc < DH; cc++) {
            float wv = W1s[cc * DA + lane];
            const float* xcol = xbase + (cc >> 6) * (4 * 32 * XPITCH) + (cc & 63);
            #pragma unroll
            for (int j = 0; j < 16; j++) acc16[j] += xcol[j * XPITCH] * wv;
        }
        float bt = __ldg(batt1 + lane);
        float gg = __ldg(g2 + lane) * invn;
        float bb = __ldg(be2 + lane);
        float w2 = __ldg(Watt2 + lane);
        float b2v = __ldg(batt2);
        #pragma unroll
        for (int j = 0; j < 16; j++) {
            float hv = tanhf((acc16[j] + bt) * gg + bb);
            float term = hv * w2;
            #pragma unroll
            for (int off = 16; off; off >>= 1)
                term += __shfl_xor_sync(0xffffffffu, term, off);
            if (lane == 0) {
                float sv = term + b2v;
                g_s[m0 + wid * 16 + j] = sv;
                sarr[wid * 16 + j] = sv;
            }
        }
    }
    __syncthreads();

    // phase S: histogram + deterministic block Z-partial
    if (tid < 128) {
        float sv = sarr[tid];
        atomicAdd(&g_hist[f2k(sv) >> 21], 1u);
        float e = expf(sv);
        #pragma unroll
        for (int off = 16; off; off >>= 1) e += __shfl_xor_sync(0xffffffffu, e, off);
        if ((tid & 31) == 0) zred[tid >> 5] = e;
    }
    __syncthreads();
    if (tid == 0)
        g_zpart[blockIdx.x] = ((zred[0] + zred[1]) + (zred[2] + zred[3]));
}

// ---------------- kernel 2: Z reduce + top-CAND candidate selection ----------------
__global__ __launch_bounds__(1024) void select_cand()
{
    extern __shared__ char sm2[];
    unsigned* hist = (unsigned*)(sm2);
    unsigned* lkey = (unsigned*)(sm2 + 8192);
    int*      lidx = (int*)(sm2 + 8192 + LCAP * 4);
    __shared__ float zp[32];
    __shared__ int sh_b, sh_cnt, sh_lc, sh_ovf, sh_cg;

    const int tid = threadIdx.x;
    if (tid == 0) { sh_lc = 0; sh_ovf = 0; }

    {   // Z: deterministic fixed-order tree over NBLK partials
        float z = (tid < NBLK) ? g_zpart[tid] : 0.f;
        #pragma unroll
        for (int off = 16; off; off >>= 1) z += __shfl_xor_sync(0xffffffffu, z, off);
        if ((tid & 31) == 0) zp[tid >> 5] = z;
    }
    __syncthreads();
    if (tid == 0) {
        float zz = 0.f;
        for (int i = 0; i < 32; i++) zz += zp[i];
        g_Z = zz;
        int cum = 0, b = 2047;
        for (; b > 0; b--) { if (cum + (int)g_hist[b] >= CAND) break; cum += (int)g_hist[b]; }
        sh_b = b; sh_cnt = cum;
    }
    __syncthreads();
    int need = CAND - sh_cnt;
    const unsigned b1 = (unsigned)sh_b;
    unsigned prefix = b1 << 21, mask = 0xFFE00000u;

    for (int i = tid; i < NTOT; i += 1024) {
        unsigned k = f2k(g_s[i]);
        if ((k >> 21) >= b1) {
            int p = atomicAdd(&sh_lc, 1);
            if (p < LCAP) { lkey[p] = k; lidx[p] = i; }
            else sh_ovf = 1;
        }
    }
    __syncthreads();
    const int lc = (sh_lc < LCAP) ? sh_lc : LCAP;
    const bool useList = (sh_ovf == 0);

    #pragma unroll
    for (int p3 = 0; p3 < 3; p3++) {
        const int shift = (p3 == 0) ? 13 : (p3 == 1) ? 5 : 0;
        const unsigned bm = (p3 == 2) ? 31u : 255u;
        __syncthreads();
        if (tid < 256) hist[tid] = 0;
        __syncthreads();
        if (useList) {
            for (int j = tid; j < lc; j += 1024) {
                unsigned k = lkey[j];
                if ((k & mask) == prefix) atomicAdd(&hist[(k >> shift) & bm], 1u);
            }
        } else {
            for (int i = tid; i < NTOT; i += 1024) {
                unsigned k = f2k(g_s[i]);
                if ((k & mask) == prefix) atomicAdd(&hist[(k >> shift) & bm], 1u);
            }
        }
        __syncthreads();
        if (tid == 0) {
            int cum = 0, b = (int)bm;
            for (; b > 0; b--) { if (cum + (int)hist[b] >= need) break; cum += (int)hist[b]; }
            sh_b = b; sh_cnt = cum;
        }
        __syncthreads();
        need -= sh_cnt;
        prefix |= ((unsigned)sh_b) << shift;
        mask |= bm << shift;
    }
    const unsigned T = prefix;   // exact key of rank-CAND element

    if (tid == 0) sh_cg = 0;
    __syncthreads();
    if (useList) {
        for (int j = tid; j < lc; j += 1024) {
            if (lkey[j] >= T) {
                int p = atomicAdd(&sh_cg, 1);
                if (p < CANDCAP) g_cand[p] = lidx[j];
            }
        }
    } else {
        for (int i = tid; i < NTOT; i += 1024) {
            if (f2k(g_s[i]) >= T) {
                int p = atomicAdd(&sh_cg, 1);
                if (p < CANDCAP) g_cand[p] = i;
            }
        }
    }
    __syncthreads();
    if (tid == 0) g_ncand = (sh_cg < CANDCAP) ? sh_cg : CANDCAP;
}

// ---------------- kernel 3: exact fp32 recompute (1024 thr: col x k-eighth) ----------------
__global__ __launch_bounds__(1024) void recompute_cand(
    const float* __restrict__ input, const float* __restrict__ W1,
    const float* __restrict__ b1, const float* __restrict__ g1, const float* __restrict__ be1,
    const float* __restrict__ Watt1, const float* __restrict__ batt1,
    const float* __restrict__ g2, const float* __restrict__ be2,
    const float* __restrict__ Watt2, const float* __restrict__ batt2)
{
    const int i = blockIdx.x;
    if (i >= g_ncand) return;
    const int row = g_cand[i];
    __shared__ float sir[DIN];
    __shared__ float partx[8][DH];
    __shared__ float xsm[DH];
    const int tid = threadIdx.x;
    const float* ir = input + (size_t)row * DIN;

    if (tid < DIN) sir[tid] = ir[tid];                 // stage input row (coalesced)
    __syncthreads();

    const int c = tid & 127, kg = tid >> 7;            // 8 k-groups of 96
    const int kb = kg * 96;
    const float* wp = W1 + (size_t)kb * DH + c;
    float a0 = 0.f, a1 = 0.f, a2 = 0.f, a3 = 0.f;
    #pragma unroll 4
    for (int k = 0; k < 96; k += 4) {
        a0 += sir[kb + k]     * wp[(size_t)k * DH];
        a1 += sir[kb + k + 1] * wp[(size_t)(k + 1) * DH];
        a2 += sir[kb + k + 2] * wp[(size_t)(k + 2) * DH];
        a3 += sir[kb + k + 3] * wp[(size_t)(k + 3) * DH];
    }
    partx[kg][c] = (a0 + a1) + (a2 + a3);
    __syncthreads();

    const float invn = rsqrtf(1.0f + 1e-5f);
    if (tid < DH) {
        float acc = ((partx[0][tid] + partx[1][tid]) + (partx[2][tid] + partx[3][tid]))
                  + ((partx[4][tid] + partx[5][tid]) + (partx[6][tid] + partx[7][tid]));
        float x = fmaxf((acc + b1[tid]) * (g1[tid] * invn) + be1[tid], 0.f);
        xsm[tid] = x;
        g_xc[i * DH + tid] = x;
    }
    __syncthreads();
    if (tid < DA) {
        float h = 0.f;
        for (int k = 0; k < DH; k++) h += xsm[k] * Watt1[k * DA + tid];
        float hv = tanhf((h + batt1[tid]) * (g2[tid] * invn) + be2[tid]);
        float t = hv * Watt2[tid];
        #pragma unroll
        for (int off = 16; off; off >>= 1) t += __shfl_xor_sync(0xffffffffu, t, off);
        if (tid == 0) g_sc[i] = t + batt2[0];
    }
}

// ---------------- kernel 4: merged tail (sort, zs, QKV, attention, Wz, fc) ----------------
#define TS_CS   0
#define TS_CI   1280
#define TS_ZS   2560
#define TS_WQ   35584
#define TS_WK   54016
#define TS_WV   72448
#define TS_ZQ   90880
#define TS_ZK   99328
#define TS_ZV   107776
#define TS_ZW   116224
#define TS_PART 124416
#define TAIL_BYTES 128512
__global__ __launch_bounds__(1024) void tail_all(
    const float* __restrict__ Wq, const float* __restrict__ Wk, const float* __restrict__ Wv,
    const float* __restrict__ Wz, const float* __restrict__ bz,
    const float* __restrict__ Wf, const float* __restrict__ bf,
    float* __restrict__ out)
{
    extern __shared__ char sm3[];
    float* cs = (float*)(sm3 + TS_CS);
    int*   ci = (int*)(sm3 + TS_CI);
    float* zs = (float*)(sm3 + TS_ZS);
    float* wq = (float*)(sm3 + TS_WQ);
    float* wk = (float*)(sm3 + TS_WK);
    float* wv = (float*)(sm3 + TS_WV);
    float* zq = (float*)(sm3 + TS_ZQ);
    float* zk = (float*)(sm3 + TS_ZK);
    float* zv = (float*)(sm3 + TS_ZV);
    float* zw = (float*)(sm3 + TS_ZW);
    float* part = (float*)(sm3 + TS_PART);
    __shared__ float aA[KSEL], w[KSEL];
    __shared__ int sel[KSEL];
    __shared__ float red[4];

    const int tid = threadIdx.x;
    const int n = g_ncand;
    const float Zs = g_Z;

    if (tid < n) { cs[tid] = g_sc[tid]; ci[tid] = g_cand[tid]; }
    for (int i = tid; i < DH * DA; i += 1024) {
        int r = i >> 5, c = i & 31;
        wq[r * 36 + c] = Wq[i];
        wk[r * 36 + c] = Wk[i];
        wv[r * 36 + c] = Wv[i];
    }
    __syncthreads();
    if (tid < n) {   // exact rank (s desc, idx asc)
        float msv = cs[tid]; int mi = ci[tid];
        int rank = 0;
        for (int j = 0; j < n; j++)
            rank += (cs[j] > msv) || (cs[j] == msv && ci[j] < mi);
        if (rank < KSEL) sel[rank] = tid;
    }
    __syncthreads();
    if (tid < KSEL) aA[tid] = expf(cs[sel[tid]]) / Zs;
    __syncthreads();
    if (tid == 0) {
        float m = aA[0];
        for (int i = 1; i < KSEL; i++) m = fmaxf(m, aA[i]);
        float ssum = 0.f;
        for (int i = 0; i < KSEL; i++) { float e = expf(aA[i] - m); w[i] = e; ssum += e; }
        float rs = 1.0f / ssum;
        for (int i = 0; i < KSEL; i++) w[i] *= rs;
    }
    __syncthreads();
    for (int e = tid; e < KSEL * DH; e += 1024) {
        int i = e >> 7, j = e & 127;
        zs[i * 129 + j] = g_xc[sel[i] * DH + j] * w[i];
    }
    __syncthreads();
    if (tid < 384) {   // zq/zk/zv GEMM: 4 rows x 4 cols per thread
        int rg = tid / 24, slot = tid % 24;
        int mat = slot >> 3, c4 = (slot & 7) << 2;
        const float* W = (mat == 0) ? wq : (mat == 1) ? wk : wv;
        float* dst = (mat == 0) ? zq : (mat == 1) ? zk : zv;
        float a0[4], a1[4], a2[4], a3[4];
        #pragma unroll
        for (int c = 0; c < 4; c++) { a0[c] = a1[c] = a2[c] = a3[c] = 0.f; }
        const float* z0 = zs + (rg * 4) * 129;
        for (int kk = 0; kk < DH; kk++) {
            float4 wv4 = *(const float4*)(W + kk * 36 + c4);
            float x0 = z0[kk], x1 = z0[129 + kk], x2 = z0[258 + kk], x3 = z0[387 + kk];
            a0[0] += x0 * wv4.x; a0[1] += x0 * wv4.y; a0[2] += x0 * wv4.z; a0[3] += x0 * wv4.w;
            a1[0] += x1 * wv4.x; a1[1] += x1 * wv4.y; a1[2] += x1 * wv4.z; a1[3] += x1 * wv4.w;
            a2[0] += x2 * wv4.x; a2[1] += x2 * wv4.y; a2[2] += x2 * wv4.z; a2[3] += x2 * wv4.w;
            a3[0] += x3 * wv4.x; a3[1] += x3 * wv4.y; a3[2] += x3 * wv4.z; a3[3] += x3 * wv4.w;
        }
        #pragma unroll
        for (int c = 0; c < 4; c++) {
            dst[(rg * 4 + 0) * 33 + c4 + c] = a0[c];
            dst[(rg * 4 + 1) * 33 + c4 + c] = a1[c];
            dst[(rg * 4 + 2) * 33 + c4 + c] = a2[c];
            dst[(rg * 4 + 3) * 33 + c4 + c] = a3[c];
        }
    }
    __syncthreads();
    {   // row attention: one warp -> 2 rows; zw in smem
        int lane = tid & 31, wd = tid >> 5;
        #pragma unroll
        for (int rr = 0; rr < 2; rr++) {
            int i = wd * 2 + rr;
            float l0 = 0, l1 = 0;
            #pragma unroll
            for (int c = 0; c < DA; c++) {
                float qv = zq[i * 33 + c];
                l0 += qv * zk[lane * 33 + c];
                l1 += qv * zk[(lane + 32) * 33 + c];
            }
            float m = fmaxf(l0, l1);
            #pragma unroll
            for (int off = 16; off; off >>= 1)
                m = fmaxf(m, __shfl_xor_sync(0xffffffffu, m, off));
            float p0 = expf(l0 - m), p1 = expf(l1 - m);
            float ss = p0 + p1;
            #pragma unroll
            for (int off = 16; off; off >>= 1) ss += __shfl_xor_sync(0xffffffffu, ss, off);
            float rs = 1.0f / ss;
            p0 *= rs; p1 *= rs;
            float acc = 0.f;
            #pragma unroll
            for (int j = 0; j < 32; j++) {
                float pj = __shfl_sync(0xffffffffu, p0, j);
                acc += pj * zv[j * 33 + lane];
            }
            #pragma unroll
            for (int j = 0; j < 32; j++) {
                float pj = __shfl_sync(0xffffffffu, p1, j);
                acc += pj * zv[(j + 32) * 33 + lane];
            }
            zw[i * DA + lane] = acc;
        }
    }
    __syncthreads();
    {   // z1 = relu(zw_flat @ Wz + bz): 8 m-groups x 128 n
        int g = tid >> 7, nn = tid & 127;
        float acc = 0.f;
        int mbase = g * 256;
        #pragma unroll 8
        for (int m = 0; m < 256; m++)
            acc += zw[mbase + m] * __ldg(Wz + (size_t)(mbase + m) * DH + nn);
        part[g * DH + nn] = acc;
    }
    __syncthreads();
    if (tid < DH) {
        float a = bz[tid];
        #pragma unroll
        for (int g = 0; g < 8; g++) a += part[g * DH + tid];
        float zv1 = fmaxf(a, 0.f) * Wf[tid];
        #pragma unroll
        for (int off = 16; off; off >>= 1) zv1 += __shfl_xor_sync(0xffffffffu, zv1, off);
        if ((tid & 31) == 0) red[tid >> 5] = zv1;
    }
    __syncthreads();
    if (tid == 0) out[0] = red[0] + red[1] + red[2] + red[3] + bf[0];
}

// ---------------- host launcher ----------------
extern "C" void kernel_launch(void* const* d_in, const int* in_sizes, int n_in,
                              void* d_out, int out_size)
{
    const float* input = (const float*)d_in[0];
    const float* W1    = (const float*)d_in[1];
    const float* b1    = (const float*)d_in[2];
    const float* g1    = (const float*)d_in[3];
    const float* be1   = (const float*)d_in[4];
    const float* Watt1 = (const float*)d_in[5];
    const float* batt1 = (const float*)d_in[6];
    const float* g2    = (const float*)d_in[7];
    const float* be2   = (const float*)d_in[8];
    const float* Watt2 = (const float*)d_in[9];
    const float* batt2 = (const float*)d_in[10];
    const float* Wq    = (const float*)d_in[11];
    const float* Wk    = (const float*)d_in[12];
    const float* Wv    = (const float*)d_in[13];
    const float* Wz    = (const float*)d_in[14];
    const float* bz    = (const float*)d_in[15];
    const float* Wf    = (const float*)d_in[16];
    const float* bf    = (const float*)d_in[17];

    static const int SEL_BYTES = 8192 + LCAP * 8;
    cudaFuncSetAttribute(fused_main_tc, cudaFuncAttributeMaxDynamicSharedMemorySize, SM_BYTES);
    cudaFuncSetAttribute(select_cand,  cudaFuncAttributeMaxDynamicSharedMemorySize, SEL_BYTES);
    cudaFuncSetAttribute(tail_all,     cudaFuncAttributeMaxDynamicSharedMemorySize, TAIL_BYTES);

    conv_w1<<<DH, 256>>>(W1, Wz);
    fused_main_tc<<<NBLK, 256, SM_BYTES>>>(input, b1, g1, be1,
                                           Watt1, batt1, g2, be2, Watt2, batt2);
    select_cand<<<1, 1024, SEL_BYTES>>>();
    recompute_cand<<<CANDCAP, 1024>>>(input, W1, b1, g1, be1,
                                      Watt1, batt1, g2, be2, Watt2, batt2);
    tail_all<<<1, 1024, TAIL_BYTES>>>(Wq, Wk, Wv, Wz, bz, Wf, bf, (float*)d_out);
}

// round 17
// speedup vs baseline: 1.0267x; 1.0267x over previous
#include <cuda_runtime.h>
#include <cuda_bf16.h>
#include <mma.h>
#include <math.h>
#include <stdint.h>

using namespace nvcuda;

#define NTOT 131072
#define DIN 768
#define DH 128
#define DA 32
#define KSEL 64
#define CAND 256
#define CANDCAP 320
#define KC 32
#define NITER 24
#define LCAP 4096
#define NBLK (NTOT / 128)

// ---------------- device scratch (allocation-free) ----------------
__device__ float          g_s[NTOT];                  // approximate attention scores
__device__ float          g_Z;                        // softmax denominator (approx)
__device__ unsigned       g_hist[2048];               // 11-bit score histogram
__device__ float          g_zpart[NBLK];              // per-block sum exp(s)
__device__ int            g_cand[CANDCAP];            // candidate row indices
__device__ int            g_ncand;                    // candidate count
__device__ float          g_sc[CANDCAP];              // exact fp32 scores of candidates
__device__ float          g_xc[CANDCAP * DH];         // exact fp32 x rows of candidates
__device__ float          g_zw[KSEL * DA];
__device__ float          g_part[16 * DH];
__device__ __nv_bfloat16  g_Wthi[DH * DIN];           // W1^T bf16  [n][k]

// ---------------- fused kernel smem map (bytes) ----------------
// mainloop: STA 128x36f = 18432; AHI 128x40 bf16 = 10240; BHI[2] 10240 per buf
#define OFF_STA 0
#define OFF_AHI 18432
#define OFF_BHI 28672
// epilogue reuse: XS = 8 warps x (32 x 76 f) = 77824 ; W1S 128x32 f = 16384
#define XPITCH 76
#define OFF_XS  0
#define OFF_W1S 77824
#define SM_BYTES 94208

__device__ __forceinline__ uint32_t smem_u32(const void* p) {
    uint32_t a;
    asm("{ .reg .u64 t; cvta.to.shared.u64 t, %1; cvt.u32.u64 %0, t; }" : "=r"(a) : "l"(p));
    return a;
}
__device__ __forceinline__ void cp16(uint32_t s, const void* g) {
    asm volatile("cp.async.cg.shared.global [%0], [%1], 16;" :: "r"(s), "l"(g));
}
__device__ __forceinline__ void cp_commit() { asm volatile("cp.async.commit_group;" ::: "memory"); }
__device__ __forceinline__ void cp_wait0()  { asm volatile("cp.async.wait_group 0;" ::: "memory"); }

__device__ __forceinline__ unsigned f2k(float f) {
    unsigned u = __float_as_uint(f);
    return u ^ ((u & 0x80000000u) ? 0xFFFFFFFFu : 0x80000000u);
}
__device__ __forceinline__ uint32_t pack2(float x, float y) {
    return (uint32_t)__bfloat16_as_ushort(__float2bfloat16(x)) |
           ((uint32_t)__bfloat16_as_ushort(__float2bfloat16(y)) << 16);
}

// ---------------- kernel 0: W1 -> bf16 transpose (tiled, coalesced) + hist zero ----------------
__global__ __launch_bounds__(1024) void conv_w1(const float* __restrict__ W1) {
    __shared__ float tile[32][33];
    const int tx = threadIdx.x, ty = threadIdx.y;
    const int n0 = blockIdx.x * 32, k0 = blockIdx.y * 32;
    if (blockIdx.x == 0 && blockIdx.y == 0) {
        int t = ty * 32 + tx;
        g_hist[t] = 0u;
        g_hist[t + 1024] = 0u;
    }
    tile[ty][tx] = W1[(size_t)(k0 + ty) * DH + n0 + tx];   // coalesced over n
    __syncthreads();
    g_Wthi[(size_t)(n0 + ty) * DIN + k0 + tx] = __float2bfloat16(tile[tx][ty]); // coalesced over k
}

// ---------------- kernel 1: 1-pass bf16 WMMA GEMM + approx s + hist/Z (R15 exact) ----------------
__global__ __launch_bounds__(256, 2) void fused_main_tc(
    const float* __restrict__ input,
    const float* __restrict__ b1, const float* __restrict__ g1, const float* __restrict__ be1,
    const float* __restrict__ Watt1, const float* __restrict__ batt1,
    const float* __restrict__ g2, const float* __restrict__ be2,
    const float* __restrict__ Watt2, const float* __restrict__ batt2)
{
    extern __shared__ char sm[];
    __shared__ float sarr[128];
    __shared__ float zred[4];
    const uint32_t su = smem_u32(sm);
    float*         staf = (float*)(sm + OFF_STA);
    __nv_bfloat16* sAhi = (__nv_bfloat16*)(sm + OFF_AHI);

    const int tid = threadIdx.x;
    const int lane = tid & 31, wid = tid >> 5;
    const int wg = wid >> 2;          // 0/1: N half
    const int w4 = wid & 3;           // 0..3: M group of 32 rows
    const int m0 = blockIdx.x * 128;

    wmma::fragment<wmma::accumulator, 16, 16, 16, float> fc[2][4];
    #pragma unroll
    for (int i = 0; i < 2; i++)
        #pragma unroll
        for (int j = 0; j < 4; j++) wmma::fill_fragment(fc[i][j], 0.0f);

    // prologue: issue chunk 0
    {
        #pragma unroll
        for (int j = 0; j < 4; j++) {                 // A: 1024 16B slots
            int t = tid + 256 * j;
            int row = t >> 3, c4 = t & 7;
            cp16(su + OFF_STA + row * 144 + c4 * 16, input + (size_t)(m0 + row) * DIN + c4 * 4);
        }
        #pragma unroll
        for (int j = 0; j < 2; j++) {                 // B hi: 512 slots
            int t = tid + 256 * j;
            int row = t >> 2, k8 = (t & 3) << 3;
            cp16(su + OFF_BHI + row * 80 + k8 * 2, g_Wthi + row * DIN + k8);
        }
        cp_commit();
    }

    const int cvr = tid >> 1, cvc = (tid & 1) << 4;   // convert: 2 thr/row, 16 floats each

    for (int c = 0; c < NITER; c++) {
        cp_wait0();
        __syncthreads();
        {   // convert STA fp32 -> bf16
            const float* sp = staf + cvr * 36 + cvc;
            __nv_bfloat16* dp = sAhi + cvr * 40 + cvc;
            #pragma unroll
            for (int q = 0; q < 2; q++) {
                float4 u0 = *(const float4*)(sp + q * 8);
                float4 u1 = *(const float4*)(sp + q * 8 + 4);
                uint4 hv;
                hv.x = pack2(u0.x, u0.y);
                hv.y = pack2(u0.z, u0.w);
                hv.z = pack2(u1.x, u1.y);
                hv.w = pack2(u1.z, u1.w);
                *(uint4*)(dp + q * 8) = hv;
            }
        }
        __syncthreads();
        if (c + 1 < NITER) {             // issue chunk c+1 (overlaps MMA below)
            const int k0 = (c + 1) * KC;
            const uint32_t bbuf = ((c + 1) & 1) * 10240u;
            #pragma unroll
            for (int j = 0; j < 4; j++) {
                int t = tid + 256 * j;
                int row = t >> 3, c4 = t & 7;
                cp16(su + OFF_STA + row * 144 + c4 * 16,
                     input + (size_t)(m0 + row) * DIN + k0 + c4 * 4);
            }
            #pragma unroll
            for (int j = 0; j < 2; j++) {
                int t = tid + 256 * j;
                int row = t >> 2, k8 = (t & 3) << 3;
                cp16(su + OFF_BHI + bbuf + row * 80 + k8 * 2, g_Wthi + row * DIN + k0 + k8);
            }
            cp_commit();
        }
        // MMA chunk c: single pass Ahi*Bhi
        const __nv_bfloat16* Bhi = (__nv_bfloat16*)(sm + OFF_BHI + (c & 1) * 10240);
        #pragma unroll
        for (int ks = 0; ks < 2; ks++) {
            wmma::fragment<wmma::matrix_a, 16, 16, 16, __nv_bfloat16, wmma::row_major> fa0, fa1;
            wmma::load_matrix_sync(fa0, sAhi + (w4 * 32 + 0)  * 40 + ks * 16, 40);
            wmma::load_matrix_sync(fa1, sAhi + (w4 * 32 + 16) * 40 + ks * 16, 40);
            #pragma unroll
            for (int nf = 0; nf < 4; nf++) {
                wmma::fragment<wmma::matrix_b, 16, 16, 16, __nv_bfloat16, wmma::col_major> fb;
                wmma::load_matrix_sync(fb, Bhi + (wg * 64 + nf * 16) * 40 + ks * 16, 40);
                wmma::mma_sync(fc[0][nf], fa0, fb, fc[0][nf]);
                wmma::mma_sync(fc[1][nf], fa1, fb, fc[1][nf]);
            }
        }
    }
    __syncthreads();

    // -------- epilogue (approx path: s only) --------
    float* xsf = (float*)(sm + OFF_XS);
    float* xs  = xsf + wid * (32 * XPITCH);
    float* W1s = (float*)(sm + OFF_W1S);

    #pragma unroll
    for (int i = 0; i < 2; i++)
        #pragma unroll
        for (int nf = 0; nf < 4; nf++)
            wmma::store_matrix_sync(xs + (i * 16) * XPITCH + nf * 16, fc[i][nf],
                                    XPITCH, wmma::mem_row_major);
    for (int i = tid; i < DH * DA; i += 256) W1s[i] = Watt1[i];
    __syncthreads();

    const float invn = rsqrtf(1.0f + 1e-5f);

    // phase A: BN + ReLU in smem only
    {
        int hr  = lane >> 4;
        int cc4 = (lane & 15) << 2;
        int c0  = wg * 64 + cc4;
        float4 b4 = __ldg((const float4*)(b1  + c0));
        float4 g4 = __ldg((const float4*)(g1  + c0));
        float4 e4 = __ldg((const float4*)(be1 + c0));
        float s0 = g4.x * invn, s1 = g4.y * invn, s2 = g4.z * invn, s3 = g4.w * invn;
        #pragma unroll
        for (int it = 0; it < 16; it++) {
            int r = it * 2 + hr;
            float4 a = *(float4*)(xs + r * XPITCH + cc4);
            float4 v;
            v.x = fmaxf((a.x + b4.x) * s0 + e4.x, 0.f);
            v.y = fmaxf((a.y + b4.y) * s1 + e4.y, 0.f);
            v.z = fmaxf((a.z + b4.z) * s2 + e4.z, 0.f);
            v.w = fmaxf((a.w + b4.w) * s3 + e4.w, 0.f);
            *(float4*)(xs + r * XPITCH + cc4) = v;
        }
    }
    __syncthreads();

    // phase H: warp wid owns rows wid*16..+15; lane = h column
    {
        float* xbase = xsf + (wid >> 1) * (32 * XPITCH) + ((wid & 1) * 16) * XPITCH;
        float acc16[16];
        #pragma unroll
        for (int j = 0; j < 16; j++) acc16[j] = 0.f;
        for (int cc = 0; cc < DH; cc++) {
            float wv = W1s[cc * DA + lane];
            const float* xcol = xbase + (cc >> 6) * (4 * 32 * XPITCH) + (cc & 63);
            #pragma unroll
            for (int j = 0; j < 16; j++) acc16[j] += xcol[j * XPITCH] * wv;
        }
        float bt = __ldg(batt1 + lane);
        float gg = __ldg(g2 + lane) * invn;
        float bb = __ldg(be2 + lane);
        float w2 = __ldg(Watt2 + lane);
        float b2v = __ldg(batt2);
        #pragma unroll
        for (int j = 0; j < 16; j++) {
            float hv = tanhf((acc16[j] + bt) * gg + bb);
            float term = hv * w2;
            #pragma unroll
            for (int off = 16; off; off >>= 1)
                term += __shfl_xor_sync(0xffffffffu, term, off);
            if (lane == 0) {
                float sv = term + b2v;
                g_s[m0 + wid * 16 + j] = sv;
                sarr[wid * 16 + j] = sv;
            }
        }
    }
    __syncthreads();

    // phase S: histogram + deterministic block Z-partial
    if (tid < 128) {
        float sv = sarr[tid];
        atomicAdd(&g_hist[f2k(sv) >> 21], 1u);
        float e = expf(sv);
        #pragma unroll
        for (int off = 16; off; off >>= 1) e += __shfl_xor_sync(0xffffffffu, e, off);
        if ((tid & 31) == 0) zred[tid >> 5] = e;
    }
    __syncthreads();
    if (tid == 0)
        g_zpart[blockIdx.x] = ((zred[0] + zred[1]) + (zred[2] + zred[3]));
}

// ---------------- kernel 2: Z reduce + top-CAND candidate selection ----------------
__global__ __launch_bounds__(1024) void select_cand()
{
    extern __shared__ char sm2[];
    unsigned* hist = (unsigned*)(sm2);
    unsigned* lkey = (unsigned*)(sm2 + 8192);
    int*      lidx = (int*)(sm2 + 8192 + LCAP * 4);
    __shared__ float zp[32];
    __shared__ int sh_b, sh_cnt, sh_lc, sh_ovf, sh_cg;

    const int tid = threadIdx.x;
    if (tid == 0) { sh_lc = 0; sh_ovf = 0; }

    {   // Z: deterministic fixed-order tree over NBLK partials
        float z = (tid < NBLK) ? g_zpart[tid] : 0.f;
        #pragma unroll
        for (int off = 16; off; off >>= 1) z += __shfl_xor_sync(0xffffffffu, z, off);
        if ((tid & 31) == 0) zp[tid >> 5] = z;
    }
    __syncthreads();
    if (tid == 0) {
        float zz = 0.f;
        for (int i = 0; i < 32; i++) zz += zp[i];
        g_Z = zz;
        int cum = 0, b = 2047;
        for (; b > 0; b--) { if (cum + (int)g_hist[b] >= CAND) break; cum += (int)g_hist[b]; }
        sh_b = b; sh_cnt = cum;
    }
    __syncthreads();
    int need = CAND - sh_cnt;
    const unsigned b1 = (unsigned)sh_b;
    unsigned prefix = b1 << 21, mask = 0xFFE00000u;

    for (int i = tid; i < NTOT; i += 1024) {
        unsigned k = f2k(g_s[i]);
        if ((k >> 21) >= b1) {
            int p = atomicAdd(&sh_lc, 1);
            if (p < LCAP) { lkey[p] = k; lidx[p] = i; }
            else sh_ovf = 1;
        }
    }
    __syncthreads();
    const int lc = (sh_lc < LCAP) ? sh_lc : LCAP;
    const bool useList = (sh_ovf == 0);

    #pragma unroll
    for (int p3 = 0; p3 < 3; p3++) {
        const int shift = (p3 == 0) ? 13 : (p3 == 1) ? 5 : 0;
        const unsigned bm = (p3 == 2) ? 31u : 255u;
        __syncthreads();
        if (tid < 256) hist[tid] = 0;
        __syncthreads();
        if (useList) {
            for (int j = tid; j < lc; j += 1024) {
                unsigned k = lkey[j];
                if ((k & mask) == prefix) atomicAdd(&hist[(k >> shift) & bm], 1u);
            }
        } else {
            for (int i = tid; i < NTOT; i += 1024) {
                unsigned k = f2k(g_s[i]);
                if ((k & mask) == prefix) atomicAdd(&hist[(k >> shift) & bm], 1u);
            }
        }
        __syncthreads();
        if (tid == 0) {
            int cum = 0, b = (int)bm;
            for (; b > 0; b--) { if (cum + (int)hist[b] >= need) break; cum += (int)hist[b]; }
            sh_b = b; sh_cnt = cum;
        }
        __syncthreads();
        need -= sh_cnt;
        prefix |= ((unsigned)sh_b) << shift;
        mask |= bm << shift;
    }
    const unsigned T = prefix;   // exact key of rank-CAND element

    if (tid == 0) sh_cg = 0;
    __syncthreads();
    if (useList) {
        for (int j = tid; j < lc; j += 1024) {
            if (lkey[j] >= T) {
                int p = atomicAdd(&sh_cg, 1);
                if (p < CANDCAP) g_cand[p] = lidx[j];
            }
        }
    } else {
        for (int i = tid; i < NTOT; i += 1024) {
            if (f2k(g_s[i]) >= T) {
                int p = atomicAdd(&sh_cg, 1);
                if (p < CANDCAP) g_cand[p] = i;
            }
        }
    }
    __syncthreads();
    if (tid == 0) g_ncand = (sh_cg < CANDCAP) ? sh_cg : CANDCAP;
}

// ---------------- kernel 3: exact fp32 recompute (1024 thr: col x k-eighth) ----------------
__global__ __launch_bounds__(1024) void recompute_cand(
    const float* __restrict__ input, const float* __restrict__ W1,
    const float* __restrict__ b1, const float* __restrict__ g1, const float* __restrict__ be1,
    const float* __restrict__ Watt1, const float* __restrict__ batt1,
    const float* __restrict__ g2, const float* __restrict__ be2,
    const float* __restrict__ Watt2, const float* __restrict__ batt2)
{
    const int i = blockIdx.x;
    if (i >= g_ncand) return;
    const int row = g_cand[i];
    __shared__ float sir[DIN];
    __shared__ float partx[8][DH];
    __shared__ float xsm[DH];
    const int tid = threadIdx.x;
    const float* ir = input + (size_t)row * DIN;

    if (tid < DIN) sir[tid] = ir[tid];
    __syncthreads();

    const int c = tid & 127, kg = tid >> 7;            // 8 k-groups of 96
    const int kb = kg * 96;
    const float* wp = W1 + (size_t)kb * DH + c;
    float a0 = 0.f, a1 = 0.f, a2 = 0.f, a3 = 0.f;
    #pragma unroll 4
    for (int k = 0; k < 96; k += 4) {
        a0 += sir[kb + k]     * wp[(size_t)k * DH];
        a1 += sir[kb + k + 1] * wp[(size_t)(k + 1) * DH];
        a2 += sir[kb + k + 2] * wp[(size_t)(k + 2) * DH];
        a3 += sir[kb + k + 3] * wp[(size_t)(k + 3) * DH];
    }
    partx[kg][c] = (a0 + a1) + (a2 + a3);
    __syncthreads();

    const float invn = rsqrtf(1.0f + 1e-5f);
    if (tid < DH) {
        float acc = ((partx[0][tid] + partx[1][tid]) + (partx[2][tid] + partx[3][tid]))
                  + ((partx[4][tid] + partx[5][tid]) + (partx[6][tid] + partx[7][tid]));
        float x = fmaxf((acc + b1[tid]) * (g1[tid] * invn) + be1[tid], 0.f);
        xsm[tid] = x;
        g_xc[i * DH + tid] = x;
    }
    __syncthreads();
    if (tid < DA) {
        float h = 0.f;
        for (int k = 0; k < DH; k++) h += xsm[k] * Watt1[k * DA + tid];
        float hv = tanhf((h + batt1[tid]) * (g2[tid] * invn) + be2[tid]);
        float t = hv * Watt2[tid];
        #pragma unroll
        for (int off = 16; off; off >>= 1) t += __shfl_xor_sync(0xffffffffu, t, off);
        if (tid == 0) g_sc[i] = t + batt2[0];
    }
}

// ---------------- kernel 4a: sort + zs + QKV + attention -> g_zw ----------------
#define TA_CS   0
#define TA_CI   1280
#define TA_ZS   2560
#define TA_WQ   35584
#define TA_WK   54016
#define TA_WV   72448
#define TA_ZQ   90880
#define TA_ZK   99328
#define TA_ZV   107776
#define TA_BYTES 116224
__global__ __launch_bounds__(1024) void tail_a(
    const float* __restrict__ Wq, const float* __restrict__ Wk, const float* __restrict__ Wv)
{
    extern __shared__ char sm3[];
    float* cs = (float*)(sm3 + TA_CS);
    int*   ci = (int*)(sm3 + TA_CI);
    float* zs = (float*)(sm3 + TA_ZS);
    float* wq = (float*)(sm3 + TA_WQ);
    float* wk = (float*)(sm3 + TA_WK);
    float* wv = (float*)(sm3 + TA_WV);
    float* zq = (float*)(sm3 + TA_ZQ);
    float* zk = (float*)(sm3 + TA_ZK);
    float* zv = (float*)(sm3 + TA_ZV);
    __shared__ float aA[KSEL], w[KSEL];
    __shared__ int sel[KSEL];

    const int tid = threadIdx.x;
    const int n = g_ncand;
    const float Zs = g_Z;

    if (tid < n) { cs[tid] = g_sc[tid]; ci[tid] = g_cand[tid]; }
    for (int i = tid; i < DH * DA; i += 1024) {
        int r = i >> 5, c = i & 31;
        wq[r * 36 + c] = Wq[i];
        wk[r * 36 + c] = Wk[i];
        wv[r * 36 + c] = Wv[i];
    }
    __syncthreads();
    if (tid < n) {   // exact rank (s desc, idx asc)
        float msv = cs[tid]; int mi = ci[tid];
        int rank = 0;
        for (int j = 0; j < n; j++)
            rank += (cs[j] > msv) || (cs[j] == msv && ci[j] < mi);
        if (rank < KSEL) sel[rank] = tid;
    }
    __syncthreads();
    if (tid < KSEL) aA[tid] = expf(cs[sel[tid]]) / Zs;
    __syncthreads();
    if (tid == 0) {
        float m = aA[0];
        for (int i = 1; i < KSEL; i++) m = fmaxf(m, aA[i]);
        float ssum = 0.f;
        for (int i = 0; i < KSEL; i++) { float e = expf(aA[i] - m); w[i] = e; ssum += e; }
        float rs = 1.0f / ssum;
        for (int i = 0; i < KSEL; i++) w[i] *= rs;
    }
    __syncthreads();
    for (int e = tid; e < KSEL * DH; e += 1024) {
        int i = e >> 7, j = e & 127;
        zs[i * 129 + j] = g_xc[sel[i] * DH + j] * w[i];
    }
    __syncthreads();
    if (tid < 384) {   // zq/zk/zv GEMM: 4 rows x 4 cols per thread
        int rg = tid / 24, slot = tid % 24;
        int mat = slot >> 3, c4 = (slot & 7) << 2;
        const float* W = (mat == 0) ? wq : (mat == 1) ? wk : wv;
        float* dst = (mat == 0) ? zq : (mat == 1) ? zk : zv;
        float a0[4], a1[4], a2[4], a3[4];
        #pragma unroll
        for (int c = 0; c < 4; c++) { a0[c] = a1[c] = a2[c] = a3[c] = 0.f; }
        const float* z0 = zs + (rg * 4) * 129;
        for (int kk = 0; kk < DH; kk++) {
            float4 wv4 = *(const float4*)(W + kk * 36 + c4);
            float x0 = z0[kk], x1 = z0[129 + kk], x2 = z0[258 + kk], x3 = z0[387 + kk];
            a0[0] += x0 * wv4.x; a0[1] += x0 * wv4.y; a0[2] += x0 * wv4.z; a0[3] += x0 * wv4.w;
            a1[0] += x1 * wv4.x; a1[1] += x1 * wv4.y; a1[2] += x1 * wv4.z; a1[3] += x1 * wv4.w;
            a2[0] += x2 * wv4.x; a2[1] += x2 * wv4.y; a2[2] += x2 * wv4.z; a2[3] += x2 * wv4.w;
            a3[0] += x3 * wv4.x; a3[1] += x3 * wv4.y; a3[2] += x3 * wv4.z; a3[3] += x3 * wv4.w;
        }
        #pragma unroll
        for (int c = 0; c < 4; c++) {
            dst[(rg * 4 + 0) * 33 + c4 + c] = a0[c];
            dst[(rg * 4 + 1) * 33 + c4 + c] = a1[c];
            dst[(rg * 4 + 2) * 33 + c4 + c] = a2[c];
            dst[(rg * 4 + 3) * 33 + c4 + c] = a3[c];
        }
    }
    __syncthreads();
    {   // row attention: one warp -> 2 rows; write g_zw
        int lane = tid & 31, wd = tid >> 5;
        #pragma unroll
        for (int rr = 0; rr < 2; rr++) {
            int i = wd * 2 + rr;
            float l0 = 0, l1 = 0;
            #pragma unroll
            for (int c = 0; c < DA; c++) {
                float qv = zq[i * 33 + c];
                l0 += qv * zk[lane * 33 + c];
                l1 += qv * zk[(lane + 32) * 33 + c];
            }
            float m = fmaxf(l0, l1);
            #pragma unroll
            for (int off = 16; off; off >>= 1)
                m = fmaxf(m, __shfl_xor_sync(0xffffffffu, m, off));
            float p0 = expf(l0 - m), p1 = expf(l1 - m);
            float ss = p0 + p1;
            #pragma unroll
            for (int off = 16; off; off >>= 1) ss += __shfl_xor_sync(0xffffffffu, ss, off);
            float rs = 1.0f / ss;
            p0 *= rs; p1 *= rs;
            float acc = 0.f;
            #pragma unroll
            for (int j = 0; j < 32; j++) {
                float pj = __shfl_sync(0xffffffffu, p0, j);
                acc += pj * zv[j * 33 + lane];
            }
            #pragma unroll
            for (int j = 0; j < 32; j++) {
                float pj = __shfl_sync(0xffffffffu, p1, j);
                acc += pj * zv[(j + 32) * 33 + lane];
            }
            g_zw[i * DA + lane] = acc;
        }
    }
}

// ---------------- kernel 4b: Wz partials (16 blocks, deterministic) ----------------
__global__ __launch_bounds__(128) void tail_b(const float* __restrict__ Wz)
{
    __shared__ float zws[128];
    const int g = blockIdx.x, n = threadIdx.x;
    const int mb = g * 128;
    zws[n] = g_zw[mb + n];
    __syncthreads();
    float acc = 0.f;
    #pragma unroll 8
    for (int m = 0; m < 128; m++)
        acc += zws[m] * __ldg(Wz + (size_t)(mb + m) * DH + n);
    g_part[g * DH + n] = acc;
}

// ---------------- kernel 4c: reduce + relu + fc ----------------
__global__ __launch_bounds__(128) void tail_c(
    const float* __restrict__ bz, const float* __restrict__ Wf,
    const float* __restrict__ bf, float* __restrict__ out)
{
    __shared__ float red[4];
    const int t = threadIdx.x;
    float a = bz[t];
    #pragma unroll
    for (int g = 0; g < 16; g++) a += g_part[g * DH + t];
    float zv = fmaxf(a, 0.f) * Wf[t];
    #pragma unroll
    for (int off = 16; off; off >>= 1) zv += __shfl_xor_sync(0xffffffffu, zv, off);
    if ((t & 31) == 0) red[t >> 5] = zv;
    __syncthreads();
    if (t == 0) out[0] = red[0] + red[1] + red[2] + red[3] + bf[0];
}

// ---------------- host launcher ----------------
extern "C" void kernel_launch(void* const* d_in, const int* in_sizes, int n_in,
                              void* d_out, int out_size)
{
    const float* input = (const float*)d_in[0];
    const float* W1    = (const float*)d_in[1];
    const float* b1    = (const float*)d_in[2];
    const float* g1    = (const float*)d_in[3];
    const float* be1   = (const float*)d_in[4];
    const float* Watt1 = (const float*)d_in[5];
    const float* batt1 = (const float*)d_in[6];
    const float* g2    = (const float*)d_in[7];
    const float* be2   = (const float*)d_in[8];
    const float* Watt2 = (const float*)d_in[9];
    const float* batt2 = (const float*)d_in[10];
    const float* Wq    = (const float*)d_in[11];
    const float* Wk    = (const float*)d_in[12];
    const float* Wv    = (const float*)d_in[13];
    const float* Wz    = (const float*)d_in[14];
    const float* bz    = (const float*)d_in[15];
    const float* Wf    = (const float*)d_in[16];
    const float* bf    = (const float*)d_in[17];

    static const int SEL_BYTES = 8192 + LCAP * 8;
    cudaFuncSetAttribute(fused_main_tc, cudaFuncAttributeMaxDynamicSharedMemorySize, SM_BYTES);
    cudaFuncSetAttribute(select_cand,  cudaFuncAttributeMaxDynamicSharedMemorySize, SEL_BYTES);
    cudaFuncSetAttribute(tail_a,       cudaFuncAttributeMaxDynamicSharedMemorySize, TA_BYTES);

    conv_w1<<<dim3(DH / 32, DIN / 32), dim3(32, 32)>>>(W1);
    fused_main_tc<<<NBLK, 256, SM_BYTES>>>(input, b1, g1, be1,
                                           Watt1, batt1, g2, be2, Watt2, batt2);
    select_cand<<<1, 1024, SEL_BYTES>>>();
    recompute_cand<<<CANDCAP, 1024>>>(input, W1, b1, g1, be1,
                                      Watt1, batt1, g2, be2, Watt2, batt2);
    tail_a<<<1, 1024, TA_BYTES>>>(Wq, Wk, Wv);
    tail_b<<<16, 128>>>(Wz);
    tail_c<<<1, 128>>>(bz, Wf, bf, (float*)d_out);
}